// round 1
// baseline (speedup 1.0000x reference)
#include <cuda_runtime.h>
#include <cstdint>
#include <cstddef>

// Problem constants (from reference setup): N=100000, D_IN=D_OUT=256, E=3.2M
#define MAXN 100352
#define D    256

// Scratch (device globals; no allocation allowed)
__device__ float g_h[(size_t)MAXN * D];   // h = x @ W^T   (~102.8 MB)
__device__ float g_deg[MAXN];
__device__ float g_drs[MAXN];

// ---------------------------------------------------------------------------
// Degree kernels
// ---------------------------------------------------------------------------
__global__ void deg_init(int N) {
    int i = blockIdx.x * blockDim.x + threadIdx.x;
    if (i < N) g_deg[i] = 1.0f;   // self loop
}

__global__ void deg_count(const int* __restrict__ src, int E) {
    int e = blockIdx.x * blockDim.x + threadIdx.x;
    if (e < E) atomicAdd(&g_deg[src[e]], 1.0f);
}

__global__ void deg_rsqrt(int N) {
    int i = blockIdx.x * blockDim.x + threadIdx.x;
    if (i < N) g_drs[i] = rsqrtf(g_deg[i]);
}

// ---------------------------------------------------------------------------
// SGEMM: g_h[M,256] = A[M,256] * B[256,256]^T   (C[i][o] = sum_k A[i][k]*B[o][k])
// 128x128 block tile, BK=16, 256 threads, 8x8 register micro-tile.
// ---------------------------------------------------------------------------
__global__ void __launch_bounds__(256, 2) sgemm_abt(const float* __restrict__ A,
                                                    const float* __restrict__ B,
                                                    int M) {
    __shared__ __align__(16) float As[16][128];
    __shared__ __align__(16) float Bs[16][128];

    const int K = D;
    const int tid = threadIdx.x;
    const int tr = tid >> 4;   // 0..15
    const int tc = tid & 15;   // 0..15
    const int brow = blockIdx.y * 128;
    const int bcol = blockIdx.x * 128;

    float acc[8][8];
#pragma unroll
    for (int i = 0; i < 8; i++)
#pragma unroll
        for (int j = 0; j < 8; j++) acc[i][j] = 0.0f;

    for (int k0 = 0; k0 < K; k0 += 16) {
        // Load A tile (128 rows x 16 k) and B tile, transposed into smem.
#pragma unroll
        for (int t = 0; t < 2; t++) {
            int idx = tid + t * 256;          // 0..511
            int row = idx >> 2;               // 0..127
            int kq  = (idx & 3) << 2;         // 0,4,8,12

            int gr = brow + row;
            float4 va = make_float4(0.f, 0.f, 0.f, 0.f);
            if (gr < M)
                va = *reinterpret_cast<const float4*>(A + (size_t)gr * K + k0 + kq);
            As[kq + 0][row] = va.x;
            As[kq + 1][row] = va.y;
            As[kq + 2][row] = va.z;
            As[kq + 3][row] = va.w;

            float4 vb = *reinterpret_cast<const float4*>(B + (size_t)(bcol + row) * K + k0 + kq);
            Bs[kq + 0][row] = vb.x;
            Bs[kq + 1][row] = vb.y;
            Bs[kq + 2][row] = vb.z;
            Bs[kq + 3][row] = vb.w;
        }
        __syncthreads();

#pragma unroll
        for (int kk = 0; kk < 16; kk++) {
            const float4* ar = reinterpret_cast<const float4*>(&As[kk][0]);
            const float4* br = reinterpret_cast<const float4*>(&Bs[kk][0]);
            float4 a0 = ar[tr], a1 = ar[16 + tr];
            float4 b0 = br[tc], b1 = br[16 + tc];
            float a[8] = {a0.x, a0.y, a0.z, a0.w, a1.x, a1.y, a1.z, a1.w};
            float b[8] = {b0.x, b0.y, b0.z, b0.w, b1.x, b1.y, b1.z, b1.w};
#pragma unroll
            for (int i = 0; i < 8; i++)
#pragma unroll
                for (int j = 0; j < 8; j++) acc[i][j] += a[i] * b[j];
        }
        __syncthreads();
    }

    // Store: rows {tr*4+i, 64+tr*4+i}, cols {bcol + tc*4 .. +3, bcol+64 + tc*4 .. +3}
#pragma unroll
    for (int gi = 0; gi < 2; gi++) {
#pragma unroll
        for (int i = 0; i < 4; i++) {
            int gr = brow + gi * 64 + tr * 4 + i;
            if (gr >= M) continue;
            int ai = gi * 4 + i;
            float4 v0 = make_float4(acc[ai][0], acc[ai][1], acc[ai][2], acc[ai][3]);
            float4 v1 = make_float4(acc[ai][4], acc[ai][5], acc[ai][6], acc[ai][7]);
            float4* crow = reinterpret_cast<float4*>(g_h + (size_t)gr * D);
            crow[(bcol >> 2) + tc]      = v0;
            crow[(bcol >> 2) + 16 + tc] = v1;
        }
    }
}

// ---------------------------------------------------------------------------
// out[i][:] = h[i][:] * (1/deg[i])    -- the self-loop term; initializes d_out
// ---------------------------------------------------------------------------
__global__ void out_init(float* __restrict__ out, int N) {
    int i = blockIdx.x * blockDim.x + threadIdx.x;    // float4 index
    int total = N * (D / 4);
    if (i >= total) return;
    int row = i >> 6;                                  // / (D/4)
    float r = g_drs[row];
    float inv = r * r;                                 // = 1/deg
    float4 v = reinterpret_cast<const float4*>(g_h)[i];
    v.x *= inv; v.y *= inv; v.z *= inv; v.w *= inv;
    reinterpret_cast<float4*>(out)[i] = v;
}

// ---------------------------------------------------------------------------
// Edge scatter: out[src[e]][:] += drs[src]*drs[dst] * h[dst[e]][:]
// One warp per edge (grid-strided). Vectorized reduction (no return trip).
// ---------------------------------------------------------------------------
__device__ __forceinline__ void red_add_v4(float4* addr, float4 v) {
    asm volatile("red.global.add.v4.f32 [%0], {%1,%2,%3,%4};"
                 :: "l"(addr), "f"(v.x), "f"(v.y), "f"(v.z), "f"(v.w)
                 : "memory");
}

__global__ void __launch_bounds__(256) edge_scatter(const int* __restrict__ src,
                                                    const int* __restrict__ dst,
                                                    float* __restrict__ out,
                                                    int E) {
    int gwarp  = (blockIdx.x * blockDim.x + threadIdx.x) >> 5;
    int lane   = threadIdx.x & 31;
    int nwarps = (gridDim.x * blockDim.x) >> 5;

    for (int e = gwarp; e < E; e += nwarps) {
        int s = __ldg(&src[e]);
        int d = __ldg(&dst[e]);
        float v = g_drs[s] * g_drs[d];

        const float4* hp = reinterpret_cast<const float4*>(g_h + (size_t)d * D);
        float4*       op = reinterpret_cast<float4*>(out + (size_t)s * D);
#pragma unroll
        for (int i = 0; i < 2; i++) {
            float4 m = hp[lane + 32 * i];
            m.x *= v; m.y *= v; m.z *= v; m.w *= v;
            red_add_v4(op + lane + 32 * i, m);
        }
    }
}

// ---------------------------------------------------------------------------
// Launch
// ---------------------------------------------------------------------------
extern "C" void kernel_launch(void* const* d_in, const int* in_sizes, int n_in,
                              void* d_out, int out_size) {
    const float* x  = (const float*)d_in[0];   // [N,256]
    const float* W  = (const float*)d_in[1];   // [256,256]
    const int*   ei = (const int*)d_in[2];     // [2,E]

    int N = in_sizes[0] / D;
    int E = in_sizes[2] / 2;
    const int* src = ei;
    const int* dst = ei + E;
    float* out = (float*)d_out;

    deg_init <<<(N + 255) / 256, 256>>>(N);
    deg_count<<<(E + 255) / 256, 256>>>(src, E);
    deg_rsqrt<<<(N + 255) / 256, 256>>>(N);

    dim3 grid(D / 128, (N + 127) / 128);
    sgemm_abt<<<grid, 256>>>(x, W, N);

    out_init<<<(N * (D / 4) + 255) / 256, 256>>>(out, N);

    edge_scatter<<<148 * 24, 256>>>(src, dst, out, E);
}

// round 2
// speedup vs baseline: 2.5463x; 2.5463x over previous
#include <cuda_runtime.h>
#include <cuda_fp16.h>
#include <cstdint>
#include <cstddef>

// Problem constants: N=100000, D_IN=D_OUT=256, E=3.2M
#define MAXN 100352
#define MAXE 3200000
#define D    256

// Scratch (device globals; allocation is forbidden)
__device__ __align__(16) __half g_h2[(size_t)MAXN * D];  // drs[j] * (x@W^T)[j], fp16 (~51.4MB)
__device__ float g_drs[MAXN];
__device__ int   g_cnt[MAXN];        // out-degree histogram (src counts, no self loop)
__device__ int   g_excl[MAXN];       // per-block exclusive scan
__device__ int   g_blksum[512];      // block sums
__device__ int   g_rowptr[MAXN + 1]; // CSR row pointers
__device__ int   g_off[MAXN];        // running fill offsets
__device__ int   g_col[MAXE];        // CSR column indices (dst sorted by src)

// ---------------------------------------------------------------------------
// Degree histogram + normalization
// ---------------------------------------------------------------------------
__global__ void cnt_zero(int N) {
    int i = blockIdx.x * blockDim.x + threadIdx.x;
    if (i < N) g_cnt[i] = 0;
}

__global__ void cnt_edges(const int* __restrict__ src, int E) {
    int e = blockIdx.x * blockDim.x + threadIdx.x;
    if (e < E) atomicAdd(&g_cnt[src[e]], 1);
}

__global__ void drs_compute(int N) {
    int i = blockIdx.x * blockDim.x + threadIdx.x;
    if (i < N) g_drs[i] = rsqrtf((float)g_cnt[i] + 1.0f);   // +1 self loop
}

// ---------------------------------------------------------------------------
// Exclusive prefix sum over g_cnt -> g_rowptr (3-phase block scan)
// ---------------------------------------------------------------------------
__global__ void scan_phase1(int N) {
    __shared__ int sh[256];
    int i = blockIdx.x * 256 + threadIdx.x;
    int v = (i < N) ? g_cnt[i] : 0;
    sh[threadIdx.x] = v;
    __syncthreads();
#pragma unroll
    for (int off = 1; off < 256; off <<= 1) {
        int t = (threadIdx.x >= off) ? sh[threadIdx.x - off] : 0;
        __syncthreads();
        sh[threadIdx.x] += t;
        __syncthreads();
    }
    if (i < N) g_excl[i] = sh[threadIdx.x] - v;           // exclusive within block
    if (threadIdx.x == 255) g_blksum[blockIdx.x] = sh[255];
}

__global__ void scan_phase2(int nb) {
    __shared__ int sh[512];
    int t = threadIdx.x;
    int v = (t < nb) ? g_blksum[t] : 0;
    sh[t] = v;
    __syncthreads();
#pragma unroll
    for (int off = 1; off < 512; off <<= 1) {
        int u = (t >= off) ? sh[t - off] : 0;
        __syncthreads();
        sh[t] += u;
        __syncthreads();
    }
    if (t < nb) g_blksum[t] = sh[t] - v;                  // exclusive block offsets
}

__global__ void scan_phase3(int N, int E) {
    int i = blockIdx.x * 256 + threadIdx.x;
    if (i < N) {
        int r = g_excl[i] + g_blksum[blockIdx.x];
        g_rowptr[i] = r;
        g_off[i] = r;
    }
    if (i == 0) g_rowptr[N] = E;
}

__global__ void build_col(const int* __restrict__ src, const int* __restrict__ dst, int E) {
    int e = blockIdx.x * blockDim.x + threadIdx.x;
    if (e < E) {
        int p = atomicAdd(&g_off[src[e]], 1);
        g_col[p] = dst[e];
    }
}

// ---------------------------------------------------------------------------
// SGEMM: g_h2[M,256] = fp16( drs[i] * (A[M,256] * B[256,256]^T) )
// 128x128 block tile, BK=16, 256 threads, 8x8 register micro-tile.
// ---------------------------------------------------------------------------
__global__ void __launch_bounds__(256, 2) sgemm_abt(const float* __restrict__ A,
                                                    const float* __restrict__ B,
                                                    int M) {
    __shared__ __align__(16) float As[16][128];
    __shared__ __align__(16) float Bs[16][128];

    const int K = D;
    const int tid = threadIdx.x;
    const int tr = tid >> 4;   // 0..15
    const int tc = tid & 15;   // 0..15
    const int brow = blockIdx.y * 128;
    const int bcol = blockIdx.x * 128;

    float acc[8][8];
#pragma unroll
    for (int i = 0; i < 8; i++)
#pragma unroll
        for (int j = 0; j < 8; j++) acc[i][j] = 0.0f;

    for (int k0 = 0; k0 < K; k0 += 16) {
#pragma unroll
        for (int t = 0; t < 2; t++) {
            int idx = tid + t * 256;
            int row = idx >> 2;
            int kq  = (idx & 3) << 2;

            int gr = brow + row;
            float4 va = make_float4(0.f, 0.f, 0.f, 0.f);
            if (gr < M)
                va = *reinterpret_cast<const float4*>(A + (size_t)gr * K + k0 + kq);
            As[kq + 0][row] = va.x;
            As[kq + 1][row] = va.y;
            As[kq + 2][row] = va.z;
            As[kq + 3][row] = va.w;

            float4 vb = *reinterpret_cast<const float4*>(B + (size_t)(bcol + row) * K + k0 + kq);
            Bs[kq + 0][row] = vb.x;
            Bs[kq + 1][row] = vb.y;
            Bs[kq + 2][row] = vb.z;
            Bs[kq + 3][row] = vb.w;
        }
        __syncthreads();

#pragma unroll
        for (int kk = 0; kk < 16; kk++) {
            const float4* ar = reinterpret_cast<const float4*>(&As[kk][0]);
            const float4* br = reinterpret_cast<const float4*>(&Bs[kk][0]);
            float4 a0 = ar[tr], a1 = ar[16 + tr];
            float4 b0 = br[tc], b1 = br[16 + tc];
            float a[8] = {a0.x, a0.y, a0.z, a0.w, a1.x, a1.y, a1.z, a1.w};
            float b[8] = {b0.x, b0.y, b0.z, b0.w, b1.x, b1.y, b1.z, b1.w};
#pragma unroll
            for (int i = 0; i < 8; i++)
#pragma unroll
                for (int j = 0; j < 8; j++) acc[i][j] += a[i] * b[j];
        }
        __syncthreads();
    }

    // Epilogue: scale by drs[row], convert to half, store.
#pragma unroll
    for (int gi = 0; gi < 2; gi++) {
#pragma unroll
        for (int i = 0; i < 4; i++) {
            int gr = brow + gi * 64 + tr * 4 + i;
            if (gr >= M) continue;
            float s = g_drs[gr];
            int ai = gi * 4 + i;
            __half2* hrow = reinterpret_cast<__half2*>(g_h2 + (size_t)gr * D);
#pragma unroll
            for (int gj = 0; gj < 2; gj++) {
                int c0 = bcol + gj * 64 + tc * 4;            // multiple of 4
                hrow[(c0 >> 1) + 0] = __floats2half2_rn(acc[ai][gj*4+0] * s, acc[ai][gj*4+1] * s);
                hrow[(c0 >> 1) + 1] = __floats2half2_rn(acc[ai][gj*4+2] * s, acc[ai][gj*4+3] * s);
            }
        }
    }
}

// ---------------------------------------------------------------------------
// Aggregation: one warp per node.
// out[i] = drs[i] * ( h2[i] + sum_{j in adj(i)} h2[j] )
// Each lane owns 8 contiguous channels (16B of fp16 per row).
// ---------------------------------------------------------------------------
__global__ void __launch_bounds__(256) aggregate(float* __restrict__ out, int N) {
    int warp = (blockIdx.x * blockDim.x + threadIdx.x) >> 5;
    int lane = threadIdx.x & 31;
    if (warp >= N) return;
    const int i = warp;

    float acc[8];
    {   // self loop
        uint4 w = *reinterpret_cast<const uint4*>(g_h2 + (size_t)i * D + lane * 8);
        const __half2* hv = reinterpret_cast<const __half2*>(&w);
#pragma unroll
        for (int q = 0; q < 4; q++) {
            float2 f = __half22float2(hv[q]);
            acc[2*q + 0] = f.x;
            acc[2*q + 1] = f.y;
        }
    }

    int s = g_rowptr[i];
    int e = g_rowptr[i + 1];
    for (int b = s; b < e; b += 32) {
        int nidx = (b + lane < e) ? g_col[b + lane] : 0;
        int cnt = min(32, e - b);
        for (int t = 0; t < cnt; t++) {
            int j = __shfl_sync(0xffffffffu, nidx, t);
            uint4 w = *reinterpret_cast<const uint4*>(g_h2 + (size_t)j * D + lane * 8);
            const __half2* hv = reinterpret_cast<const __half2*>(&w);
#pragma unroll
            for (int q = 0; q < 4; q++) {
                float2 f = __half22float2(hv[q]);
                acc[2*q + 0] += f.x;
                acc[2*q + 1] += f.y;
            }
        }
    }

    float r = g_drs[i];
    float4 v0 = make_float4(acc[0]*r, acc[1]*r, acc[2]*r, acc[3]*r);
    float4 v1 = make_float4(acc[4]*r, acc[5]*r, acc[6]*r, acc[7]*r);
    float* orow = out + (size_t)i * D + lane * 8;
    *reinterpret_cast<float4*>(orow)     = v0;
    *reinterpret_cast<float4*>(orow + 4) = v1;
}

// ---------------------------------------------------------------------------
// Launch
// ---------------------------------------------------------------------------
extern "C" void kernel_launch(void* const* d_in, const int* in_sizes, int n_in,
                              void* d_out, int out_size) {
    const float* x  = (const float*)d_in[0];   // [N,256]
    const float* W  = (const float*)d_in[1];   // [256,256]
    const int*   ei = (const int*)d_in[2];     // [2,E]

    int N = in_sizes[0] / D;
    int E = in_sizes[2] / 2;
    const int* src = ei;
    const int* dst = ei + E;
    float* out = (float*)d_out;

    int nbN = (N + 255) / 256;
    int nbE = (E + 255) / 256;

    cnt_zero   <<<nbN, 256>>>(N);
    cnt_edges  <<<nbE, 256>>>(src, E);
    drs_compute<<<nbN, 256>>>(N);

    scan_phase1<<<nbN, 256>>>(N);
    scan_phase2<<<1,   512>>>(nbN);
    scan_phase3<<<nbN, 256>>>(N, E);
    build_col  <<<nbE, 256>>>(src, dst, E);

    dim3 grid(D / 128, (N + 127) / 128);
    sgemm_abt<<<grid, 256>>>(x, W, N);

    aggregate<<<(N + 7) / 8, 256>>>(out, N);
}

// round 3
// speedup vs baseline: 4.3460x; 1.7068x over previous
#include <cuda_runtime.h>
#include <cuda_fp16.h>
#include <cstdint>
#include <cstddef>

// Problem constants: N=100000, D_IN=D_OUT=256, E=3.2M
#define MAXN 100352
#define MAXE 3200000
#define D    256

// Scratch (device globals; allocation is forbidden)
__device__ __align__(16) __half g_h2[(size_t)MAXN * D];  // drs[j] * (x@W^T)[j], fp16 (~51.4MB)
__device__ float g_drs[MAXN];
__device__ int   g_cnt[MAXN];
__device__ int   g_excl[MAXN];
__device__ int   g_blksum[512];
__device__ int   g_rowptr[MAXN + 1];
__device__ int   g_off[MAXN];
__device__ int   g_col[MAXE];

__device__ __forceinline__ uint32_t smem_u32(const void* p) {
    return (uint32_t)__cvta_generic_to_shared(p);
}

// ---------------------------------------------------------------------------
// Degree histogram + normalization
// ---------------------------------------------------------------------------
__global__ void cnt_zero(int N) {
    int i = blockIdx.x * blockDim.x + threadIdx.x;
    if (i < N) g_cnt[i] = 0;
}

__global__ void cnt_edges(const int* __restrict__ src, int E) {
    int e = blockIdx.x * blockDim.x + threadIdx.x;
    if (e < E) atomicAdd(&g_cnt[src[e]], 1);
}

__global__ void drs_compute(int N) {
    int i = blockIdx.x * blockDim.x + threadIdx.x;
    if (i < N) g_drs[i] = rsqrtf((float)g_cnt[i] + 1.0f);   // +1 self loop
}

// ---------------------------------------------------------------------------
// Exclusive prefix sum over g_cnt -> g_rowptr
// ---------------------------------------------------------------------------
__global__ void scan_phase1(int N) {
    __shared__ int sh[256];
    int i = blockIdx.x * 256 + threadIdx.x;
    int v = (i < N) ? g_cnt[i] : 0;
    sh[threadIdx.x] = v;
    __syncthreads();
#pragma unroll
    for (int off = 1; off < 256; off <<= 1) {
        int t = (threadIdx.x >= off) ? sh[threadIdx.x - off] : 0;
        __syncthreads();
        sh[threadIdx.x] += t;
        __syncthreads();
    }
    if (i < N) g_excl[i] = sh[threadIdx.x] - v;
    if (threadIdx.x == 255) g_blksum[blockIdx.x] = sh[255];
}

__global__ void scan_phase2(int nb) {
    __shared__ int sh[512];
    int t = threadIdx.x;
    int v = (t < nb) ? g_blksum[t] : 0;
    sh[t] = v;
    __syncthreads();
#pragma unroll
    for (int off = 1; off < 512; off <<= 1) {
        int u = (t >= off) ? sh[t - off] : 0;
        __syncthreads();
        sh[t] += u;
        __syncthreads();
    }
    if (t < nb) g_blksum[t] = sh[t] - v;
}

__global__ void scan_phase3(int N, int E) {
    int i = blockIdx.x * 256 + threadIdx.x;
    if (i < N) {
        int r = g_excl[i] + g_blksum[blockIdx.x];
        g_rowptr[i] = r;
        g_off[i] = r;
    }
    if (i == 0) g_rowptr[N] = E;
}

__global__ void build_col(const int* __restrict__ src, const int* __restrict__ dst, int E) {
    int e = blockIdx.x * blockDim.x + threadIdx.x;
    if (e < E) {
        int p = atomicAdd(&g_off[src[e]], 1);
        g_col[p] = dst[e];
    }
}

// ---------------------------------------------------------------------------
// Tensor-core HGEMM: g_h2[M,256] = fp16( drs[i] * (A[M,256] @ W[256,256]^T) )
// fp32 inputs converted to fp16 at smem-store. mma.m16n8k16 fp32 accumulate.
// 128x128 block tile, BK=32, 8 warps (2x4), 64x32 warp tile.
// ---------------------------------------------------------------------------
__global__ void __launch_bounds__(256, 2) hgemm_abt(const float* __restrict__ A,
                                                    const float* __restrict__ Wm,
                                                    int M) {
    __shared__ __align__(16) __half As[128][40];   // +8 halves pad: 80B row stride
    __shared__ __align__(16) __half Bs[128][40];

    const int tid  = threadIdx.x;
    const int lane = tid & 31;
    const int wid  = tid >> 5;
    const int wm   = wid >> 2;       // 0..1  (64 rows each)
    const int wn   = wid & 3;        // 0..3  (32 cols each)
    const int brow = blockIdx.y * 128;
    const int bcol = blockIdx.x * 128;

    float acc[4][4][4];
#pragma unroll
    for (int mt = 0; mt < 4; mt++)
#pragma unroll
        for (int nt = 0; nt < 4; nt++)
#pragma unroll
            for (int q = 0; q < 4; q++) acc[mt][nt][q] = 0.0f;

    for (int k0 = 0; k0 < 256; k0 += 32) {
        // Load 128x32 fp32 tiles of A and W, convert to fp16 into smem.
#pragma unroll
        for (int t = 0; t < 4; t++) {
            int idx = tid + t * 256;        // 0..1023
            int row = idx >> 3;             // 0..127
            int cf  = idx & 7;              // float4 column 0..7

            int gr = brow + row;
            float4 v = make_float4(0.f, 0.f, 0.f, 0.f);
            if (gr < M)
                v = *reinterpret_cast<const float4*>(A + (size_t)gr * 256 + k0 + cf * 4);
            __half2* da = reinterpret_cast<__half2*>(&As[row][cf * 4]);
            da[0] = __floats2half2_rn(v.x, v.y);
            da[1] = __floats2half2_rn(v.z, v.w);

            float4 u = *reinterpret_cast<const float4*>(Wm + (size_t)(bcol + row) * 256 + k0 + cf * 4);
            __half2* db = reinterpret_cast<__half2*>(&Bs[row][cf * 4]);
            db[0] = __floats2half2_rn(u.x, u.y);
            db[1] = __floats2half2_rn(u.z, u.w);
        }
        __syncthreads();

#pragma unroll
        for (int ks = 0; ks < 2; ks++) {
            uint32_t a[4][4], b[4][2];
#pragma unroll
            for (int mt = 0; mt < 4; mt++) {
                uint32_t addr = smem_u32(&As[wm * 64 + mt * 16 + (lane & 15)]
                                            [ks * 16 + (lane >> 4) * 8]);
                asm volatile("ldmatrix.sync.aligned.m8n8.x4.shared.b16 {%0,%1,%2,%3}, [%4];"
                             : "=r"(a[mt][0]), "=r"(a[mt][1]), "=r"(a[mt][2]), "=r"(a[mt][3])
                             : "r"(addr));
            }
#pragma unroll
            for (int nt = 0; nt < 4; nt++) {
                int l16 = lane & 15;
                uint32_t addr = smem_u32(&Bs[wn * 32 + nt * 8 + (l16 & 7)]
                                            [ks * 16 + (l16 >> 3) * 8]);
                asm volatile("ldmatrix.sync.aligned.m8n8.x2.shared.b16 {%0,%1}, [%2];"
                             : "=r"(b[nt][0]), "=r"(b[nt][1])
                             : "r"(addr));
            }
#pragma unroll
            for (int mt = 0; mt < 4; mt++)
#pragma unroll
                for (int nt = 0; nt < 4; nt++)
                    asm volatile(
                        "mma.sync.aligned.m16n8k16.row.col.f32.f16.f16.f32 "
                        "{%0,%1,%2,%3},{%4,%5,%6,%7},{%8,%9},{%0,%1,%2,%3};"
                        : "+f"(acc[mt][nt][0]), "+f"(acc[mt][nt][1]),
                          "+f"(acc[mt][nt][2]), "+f"(acc[mt][nt][3])
                        : "r"(a[mt][0]), "r"(a[mt][1]), "r"(a[mt][2]), "r"(a[mt][3]),
                          "r"(b[nt][0]), "r"(b[nt][1]));
        }
        __syncthreads();
    }

    // Epilogue: scale rows by drs, convert fp16, store to g_h2.
    const int tg = lane >> 2, tq = lane & 3;
#pragma unroll
    for (int mt = 0; mt < 4; mt++) {
        int r0 = brow + wm * 64 + mt * 16 + tg;
        int r1 = r0 + 8;
        float s0 = (r0 < M) ? g_drs[r0] : 0.f;
        float s1 = (r1 < M) ? g_drs[r1] : 0.f;
#pragma unroll
        for (int nt = 0; nt < 4; nt++) {
            int c = bcol + wn * 32 + nt * 8 + tq * 2;
            if (r0 < M)
                *reinterpret_cast<__half2*>(g_h2 + (size_t)r0 * D + c) =
                    __floats2half2_rn(acc[mt][nt][0] * s0, acc[mt][nt][1] * s0);
            if (r1 < M)
                *reinterpret_cast<__half2*>(g_h2 + (size_t)r1 * D + c) =
                    __floats2half2_rn(acc[mt][nt][2] * s1, acc[mt][nt][3] * s1);
        }
    }
}

// ---------------------------------------------------------------------------
// Aggregation: one warp per node.
// out[i] = drs[i] * ( h2[i] + sum_{j in adj(i)} h2[j] )
// ---------------------------------------------------------------------------
__global__ void __launch_bounds__(256) aggregate(float* __restrict__ out, int N) {
    int warp = (blockIdx.x * blockDim.x + threadIdx.x) >> 5;
    int lane = threadIdx.x & 31;
    if (warp >= N) return;
    const int i = warp;

    float acc[8];
    {   // self loop
        uint4 w = *reinterpret_cast<const uint4*>(g_h2 + (size_t)i * D + lane * 8);
        const __half2* hv = reinterpret_cast<const __half2*>(&w);
#pragma unroll
        for (int q = 0; q < 4; q++) {
            float2 f = __half22float2(hv[q]);
            acc[2*q + 0] = f.x;
            acc[2*q + 1] = f.y;
        }
    }

    int s = g_rowptr[i];
    int e = g_rowptr[i + 1];
    for (int b = s; b < e; b += 32) {
        int nidx = (b + lane < e) ? g_col[b + lane] : 0;
        int cnt = min(32, e - b);
        for (int t = 0; t < cnt; t++) {
            int j = __shfl_sync(0xffffffffu, nidx, t);
            uint4 w = *reinterpret_cast<const uint4*>(g_h2 + (size_t)j * D + lane * 8);
            const __half2* hv = reinterpret_cast<const __half2*>(&w);
#pragma unroll
            for (int q = 0; q < 4; q++) {
                float2 f = __half22float2(hv[q]);
                acc[2*q + 0] += f.x;
                acc[2*q + 1] += f.y;
            }
        }
    }

    float r = g_drs[i];
    float4 v0 = make_float4(acc[0]*r, acc[1]*r, acc[2]*r, acc[3]*r);
    float4 v1 = make_float4(acc[4]*r, acc[5]*r, acc[6]*r, acc[7]*r);
    float* orow = out + (size_t)i * D + lane * 8;
    *reinterpret_cast<float4*>(orow)     = v0;
    *reinterpret_cast<float4*>(orow + 4) = v1;
}

// ---------------------------------------------------------------------------
// Launch
// ---------------------------------------------------------------------------
extern "C" void kernel_launch(void* const* d_in, const int* in_sizes, int n_in,
                              void* d_out, int out_size) {
    const float* x  = (const float*)d_in[0];   // [N,256]
    const float* W  = (const float*)d_in[1];   // [256,256]
    const int*   ei = (const int*)d_in[2];     // [2,E]

    int N = in_sizes[0] / D;
    int E = in_sizes[2] / 2;
    const int* src = ei;
    const int* dst = ei + E;
    float* out = (float*)d_out;

    int nbN = (N + 255) / 256;
    int nbE = (E + 255) / 256;

    cnt_zero   <<<nbN, 256>>>(N);
    cnt_edges  <<<nbE, 256>>>(src, E);
    drs_compute<<<nbN, 256>>>(N);

    scan_phase1<<<nbN, 256>>>(N);
    scan_phase2<<<1,   512>>>(nbN);
    scan_phase3<<<nbN, 256>>>(N, E);
    build_col  <<<nbE, 256>>>(src, dst, E);

    dim3 grid(D / 128, (N + 127) / 128);
    hgemm_abt<<<grid, 256>>>(x, W, N);

    aggregate<<<(N + 7) / 8, 256>>>(out, N);
}

// round 4
// speedup vs baseline: 4.8629x; 1.1189x over previous
#include <cuda_runtime.h>
#include <cuda_fp16.h>
#include <cstdint>
#include <cstddef>

// Problem constants: N=100000, D_IN=D_OUT=256, E=3.2M
#define MAXN 100352
#define MAXE 3200000
#define D    256

// Scratch (device globals; allocation is forbidden)
__device__ __align__(16) __half g_h2[(size_t)MAXN * D];  // drs[j] * (x@W^T)[j], fp16
__device__ float g_drs[MAXN];
__device__ int   g_cnt[MAXN];
__device__ int   g_excl[MAXN];
__device__ int   g_blksum[512];
__device__ int   g_rowptr[MAXN + 1];
__device__ int   g_off[MAXN];
__device__ int   g_col[MAXE];

__device__ __forceinline__ uint32_t smem_u32(const void* p) {
    return (uint32_t)__cvta_generic_to_shared(p);
}

// ---------------------------------------------------------------------------
// Degree histogram
// ---------------------------------------------------------------------------
__global__ void cnt_zero(int N) {
    int i = blockIdx.x * blockDim.x + threadIdx.x;
    if (i < N) g_cnt[i] = 0;
}

__global__ void cnt_edges(const int* __restrict__ src, int E) {
    int e = blockIdx.x * blockDim.x + threadIdx.x;
    if (e < E) atomicAdd(&g_cnt[src[e]], 1);
}

// ---------------------------------------------------------------------------
// Prefix sum over g_cnt -> g_rowptr (+ fused drs = rsqrt(deg+1))
// ---------------------------------------------------------------------------
__global__ void scan_phase1(int N) {
    __shared__ int sh[256];
    int i = blockIdx.x * 256 + threadIdx.x;
    int v = (i < N) ? g_cnt[i] : 0;
    if (i < N) g_drs[i] = rsqrtf((float)v + 1.0f);   // fused normalization
    sh[threadIdx.x] = v;
    __syncthreads();
#pragma unroll
    for (int off = 1; off < 256; off <<= 1) {
        int t = (threadIdx.x >= off) ? sh[threadIdx.x - off] : 0;
        __syncthreads();
        sh[threadIdx.x] += t;
        __syncthreads();
    }
    if (i < N) g_excl[i] = sh[threadIdx.x] - v;
    if (threadIdx.x == 255) g_blksum[blockIdx.x] = sh[255];
}

__global__ void scan_phase2(int nb) {
    __shared__ int sh[512];
    int t = threadIdx.x;
    int v = (t < nb) ? g_blksum[t] : 0;
    sh[t] = v;
    __syncthreads();
#pragma unroll
    for (int off = 1; off < 512; off <<= 1) {
        int u = (t >= off) ? sh[t - off] : 0;
        __syncthreads();
        sh[t] += u;
        __syncthreads();
    }
    if (t < nb) g_blksum[t] = sh[t] - v;
}

__global__ void scan_phase3(int N, int E) {
    int i = blockIdx.x * 256 + threadIdx.x;
    if (i < N) {
        int r = g_excl[i] + g_blksum[blockIdx.x];
        g_rowptr[i] = r;
        g_off[i] = r;
    }
    if (i == 0) g_rowptr[N] = E;
}

__global__ void build_col(const int* __restrict__ src, const int* __restrict__ dst, int E) {
    int e = blockIdx.x * blockDim.x + threadIdx.x;
    if (e < E) {
        int p = atomicAdd(&g_off[src[e]], 1);
        g_col[p] = dst[e];
    }
}

// ---------------------------------------------------------------------------
// Pipelined tensor-core HGEMM: g_h2 = fp16( drs[i] * (A @ W^T) )
// 128x128 block tile, BK=16, 8 warps (2x4), register-prefetch pipeline.
// ---------------------------------------------------------------------------
__global__ void __launch_bounds__(256, 2) hgemm_abt(const float* __restrict__ A,
                                                    const float* __restrict__ Wm,
                                                    int M) {
    __shared__ __align__(16) __half As[128][24];   // 48B row stride: conflict-free phases
    __shared__ __align__(16) __half Bs[128][24];

    const int tid  = threadIdx.x;
    const int lane = tid & 31;
    const int wid  = tid >> 5;
    const int wm   = wid >> 2;       // 0..1
    const int wn   = wid & 3;        // 0..3
    const int brow = blockIdx.y * 128;
    const int bcol = blockIdx.x * 128;

    // Per-thread tile-load coordinates (two chunks of 256 threads cover 128x16 fp32)
    const int r0c = (tid)       >> 2;          // rows 0..63
    const int r1c = (tid + 256) >> 2;          // rows 64..127
    const int cf0 = (tid & 3) * 4;             // k offset within BK

    float acc[4][4][4];
#pragma unroll
    for (int mt = 0; mt < 4; mt++)
#pragma unroll
        for (int nt = 0; nt < 4; nt++)
#pragma unroll
            for (int q = 0; q < 4; q++) acc[mt][nt][q] = 0.0f;

    // Prefetch k0 = 0 tile into registers
    float4 pa0, pa1, pb0, pb1;
    {
        int ga0 = brow + r0c, ga1 = brow + r1c;
        pa0 = (ga0 < M) ? *reinterpret_cast<const float4*>(A + (size_t)ga0 * 256 + cf0)
                        : make_float4(0.f, 0.f, 0.f, 0.f);
        pa1 = (ga1 < M) ? *reinterpret_cast<const float4*>(A + (size_t)ga1 * 256 + cf0)
                        : make_float4(0.f, 0.f, 0.f, 0.f);
        pb0 = *reinterpret_cast<const float4*>(Wm + (size_t)(bcol + r0c) * 256 + cf0);
        pb1 = *reinterpret_cast<const float4*>(Wm + (size_t)(bcol + r1c) * 256 + cf0);
    }

#pragma unroll 4
    for (int k0 = 0; k0 < 256; k0 += 16) {
        // Stage prefetched tile into smem (fp32 -> fp16)
        {
            __half2* da0 = reinterpret_cast<__half2*>(&As[r0c][cf0]);
            da0[0] = __floats2half2_rn(pa0.x, pa0.y);
            da0[1] = __floats2half2_rn(pa0.z, pa0.w);
            __half2* da1 = reinterpret_cast<__half2*>(&As[r1c][cf0]);
            da1[0] = __floats2half2_rn(pa1.x, pa1.y);
            da1[1] = __floats2half2_rn(pa1.z, pa1.w);
            __half2* db0 = reinterpret_cast<__half2*>(&Bs[r0c][cf0]);
            db0[0] = __floats2half2_rn(pb0.x, pb0.y);
            db0[1] = __floats2half2_rn(pb0.z, pb0.w);
            __half2* db1 = reinterpret_cast<__half2*>(&Bs[r1c][cf0]);
            db1[0] = __floats2half2_rn(pb1.x, pb1.y);
            db1[1] = __floats2half2_rn(pb1.z, pb1.w);
        }
        __syncthreads();

        // Issue next tile's global loads (latency hidden by the MMAs below)
        if (k0 + 16 < 256) {
            int kn = k0 + 16;
            int ga0 = brow + r0c, ga1 = brow + r1c;
            pa0 = (ga0 < M) ? *reinterpret_cast<const float4*>(A + (size_t)ga0 * 256 + kn + cf0)
                            : make_float4(0.f, 0.f, 0.f, 0.f);
            pa1 = (ga1 < M) ? *reinterpret_cast<const float4*>(A + (size_t)ga1 * 256 + kn + cf0)
                            : make_float4(0.f, 0.f, 0.f, 0.f);
            pb0 = *reinterpret_cast<const float4*>(Wm + (size_t)(bcol + r0c) * 256 + kn + cf0);
            pb1 = *reinterpret_cast<const float4*>(Wm + (size_t)(bcol + r1c) * 256 + kn + cf0);
        }

        // MMA on current smem tile (k depth 16)
        uint32_t a[4][4], b[4][2];
#pragma unroll
        for (int mt = 0; mt < 4; mt++) {
            uint32_t addr = smem_u32(&As[wm * 64 + mt * 16 + (lane & 15)][(lane >> 4) * 8]);
            asm volatile("ldmatrix.sync.aligned.m8n8.x4.shared.b16 {%0,%1,%2,%3}, [%4];"
                         : "=r"(a[mt][0]), "=r"(a[mt][1]), "=r"(a[mt][2]), "=r"(a[mt][3])
                         : "r"(addr));
        }
#pragma unroll
        for (int nt = 0; nt < 4; nt++) {
            int l16 = lane & 15;
            uint32_t addr = smem_u32(&Bs[wn * 32 + nt * 8 + (l16 & 7)][(l16 >> 3) * 8]);
            asm volatile("ldmatrix.sync.aligned.m8n8.x2.shared.b16 {%0,%1}, [%2];"
                         : "=r"(b[nt][0]), "=r"(b[nt][1])
                         : "r"(addr));
        }
#pragma unroll
        for (int mt = 0; mt < 4; mt++)
#pragma unroll
            for (int nt = 0; nt < 4; nt++)
                asm volatile(
                    "mma.sync.aligned.m16n8k16.row.col.f32.f16.f16.f32 "
                    "{%0,%1,%2,%3},{%4,%5,%6,%7},{%8,%9},{%0,%1,%2,%3};"
                    : "+f"(acc[mt][nt][0]), "+f"(acc[mt][nt][1]),
                      "+f"(acc[mt][nt][2]), "+f"(acc[mt][nt][3])
                    : "r"(a[mt][0]), "r"(a[mt][1]), "r"(a[mt][2]), "r"(a[mt][3]),
                      "r"(b[nt][0]), "r"(b[nt][1]));
        __syncthreads();
    }

    // Epilogue: scale rows by drs, convert fp16, store to g_h2.
    const int tg = lane >> 2, tq = lane & 3;
#pragma unroll
    for (int mt = 0; mt < 4; mt++) {
        int r0 = brow + wm * 64 + mt * 16 + tg;
        int r1 = r0 + 8;
        float s0 = (r0 < M) ? g_drs[r0] : 0.f;
        float s1 = (r1 < M) ? g_drs[r1] : 0.f;
#pragma unroll
        for (int nt = 0; nt < 4; nt++) {
            int c = bcol + wn * 32 + nt * 8 + tq * 2;
            if (r0 < M)
                *reinterpret_cast<__half2*>(g_h2 + (size_t)r0 * D + c) =
                    __floats2half2_rn(acc[mt][nt][0] * s0, acc[mt][nt][1] * s0);
            if (r1 < M)
                *reinterpret_cast<__half2*>(g_h2 + (size_t)r1 * D + c) =
                    __floats2half2_rn(acc[mt][nt][2] * s1, acc[mt][nt][3] * s1);
        }
    }
}

// ---------------------------------------------------------------------------
// Aggregation: one warp per node, 4-way unrolled neighbor gather (MLP=4).
// out[i] = drs[i] * ( h2[i] + sum_{j in adj(i)} h2[j] )
// ---------------------------------------------------------------------------
__global__ void __launch_bounds__(256) aggregate(float* __restrict__ out, int N) {
    int warp = (blockIdx.x * blockDim.x + threadIdx.x) >> 5;
    int lane = threadIdx.x & 31;
    if (warp >= N) return;
    const int i = warp;

    float acc[8];
    {   // self loop
        uint4 w = *reinterpret_cast<const uint4*>(g_h2 + (size_t)i * D + lane * 8);
        const __half2* hv = reinterpret_cast<const __half2*>(&w);
#pragma unroll
        for (int q = 0; q < 4; q++) {
            float2 f = __half22float2(hv[q]);
            acc[2*q + 0] = f.x;
            acc[2*q + 1] = f.y;
        }
    }

    int s = g_rowptr[i];
    int e = g_rowptr[i + 1];
    for (int b = s; b < e; b += 32) {
        int nidx = (b + lane < e) ? g_col[b + lane] : 0;
        int cnt = min(32, e - b);
        int t = 0;
        for (; t + 4 <= cnt; t += 4) {
            int j0 = __shfl_sync(0xffffffffu, nidx, t + 0);
            int j1 = __shfl_sync(0xffffffffu, nidx, t + 1);
            int j2 = __shfl_sync(0xffffffffu, nidx, t + 2);
            int j3 = __shfl_sync(0xffffffffu, nidx, t + 3);
            uint4 w0 = *reinterpret_cast<const uint4*>(g_h2 + (size_t)j0 * D + lane * 8);
            uint4 w1 = *reinterpret_cast<const uint4*>(g_h2 + (size_t)j1 * D + lane * 8);
            uint4 w2 = *reinterpret_cast<const uint4*>(g_h2 + (size_t)j2 * D + lane * 8);
            uint4 w3 = *reinterpret_cast<const uint4*>(g_h2 + (size_t)j3 * D + lane * 8);
            const __half2* h0 = reinterpret_cast<const __half2*>(&w0);
            const __half2* h1 = reinterpret_cast<const __half2*>(&w1);
            const __half2* h2 = reinterpret_cast<const __half2*>(&w2);
            const __half2* h3 = reinterpret_cast<const __half2*>(&w3);
#pragma unroll
            for (int q = 0; q < 4; q++) {
                float2 f0 = __half22float2(h0[q]);
                float2 f1 = __half22float2(h1[q]);
                float2 f2 = __half22float2(h2[q]);
                float2 f3 = __half22float2(h3[q]);
                acc[2*q + 0] += (f0.x + f1.x) + (f2.x + f3.x);
                acc[2*q + 1] += (f0.y + f1.y) + (f2.y + f3.y);
            }
        }
        for (; t < cnt; t++) {
            int j = __shfl_sync(0xffffffffu, nidx, t);
            uint4 w = *reinterpret_cast<const uint4*>(g_h2 + (size_t)j * D + lane * 8);
            const __half2* hv = reinterpret_cast<const __half2*>(&w);
#pragma unroll
            for (int q = 0; q < 4; q++) {
                float2 f = __half22float2(hv[q]);
                acc[2*q + 0] += f.x;
                acc[2*q + 1] += f.y;
            }
        }
    }

    float r = g_drs[i];
    float4 v0 = make_float4(acc[0]*r, acc[1]*r, acc[2]*r, acc[3]*r);
    float4 v1 = make_float4(acc[4]*r, acc[5]*r, acc[6]*r, acc[7]*r);
    float* orow = out + (size_t)i * D + lane * 8;
    *reinterpret_cast<float4*>(orow)     = v0;
    *reinterpret_cast<float4*>(orow + 4) = v1;
}

// ---------------------------------------------------------------------------
// Launch
// ---------------------------------------------------------------------------
extern "C" void kernel_launch(void* const* d_in, const int* in_sizes, int n_in,
                              void* d_out, int out_size) {
    const float* x  = (const float*)d_in[0];   // [N,256]
    const float* W  = (const float*)d_in[1];   // [256,256]
    const int*   ei = (const int*)d_in[2];     // [2,E]

    int N = in_sizes[0] / D;
    int E = in_sizes[2] / 2;
    const int* src = ei;
    const int* dst = ei + E;
    float* out = (float*)d_out;

    int nbN = (N + 255) / 256;
    int nbE = (E + 255) / 256;

    cnt_zero   <<<nbN, 256>>>(N);
    cnt_edges  <<<nbE, 256>>>(src, E);

    scan_phase1<<<nbN, 256>>>(N);
    scan_phase2<<<1,   512>>>(nbN);
    scan_phase3<<<nbN, 256>>>(N, E);
    build_col  <<<nbE, 256>>>(src, dst, E);

    dim3 grid(D / 128, (N + 127) / 128);
    hgemm_abt<<<grid, 256>>>(x, W, N);

    aggregate<<<(N + 7) / 8, 256>>>(out, N);
}